// round 16
// baseline (speedup 1.0000x reference)
#include <cuda_runtime.h>
#include <cuda_bf16.h>
#include <cstdint>

// ---------------- problem constants ----------------
static constexpr int N_ = 50000;
static constexpr int E_ = 600000;
static constexpr int G_ = 256;
static constexpr int D_ = 128;
static constexpr int L_ = 5;
static constexpr int V_ = 128;

static constexpr int MBLKS = (N_ + 127) / 128;   // 391

// ---------------- scratch (static device globals; no runtime alloc) --------
__device__ float d_h   [N_ * D_];
__device__ float d_hsum[N_ * D_];
__device__ float d_z1  [N_ * 2 * D_];
__device__ float d_hpre[N_ * D_];
__device__ float d_stats[L_ * 1024];
__device__ float d_pool[G_ * D_];
__device__ float d_cnt [G_];
__device__ float d_zf1 [G_ * 1024];
__device__ float d_zf2 [G_ * 1024];
__device__ float d_zf3 [G_ * 512];

// pre-split GEMM1 A operand (written by k_gather)
__device__ __nv_bfloat16 d_Ah[N_ * D_];
__device__ __nv_bfloat16 d_Al[N_ * D_];

// CSR edge structures
__device__ int  d_deg   [N_];
__device__ int  d_rowptr[N_ + 1];
__device__ int  d_woff  [N_];
__device__ int4 d_epack [E_];

// bf16 weights (row-major W^T)
__device__ __nv_bfloat16 d_Wh[65536];   // W1^T [256,128] @0, W2^T [128,256] @32768

__device__ __forceinline__ float* buf(int id) {
    switch (id) {
        case 0:  return d_h;
        case 1:  return d_hsum;
        case 3:  return d_z1;
        case 4:  return d_hpre;
        case 5:  return d_stats;
        case 10: return d_pool;
        case 11: return d_cnt;
        case 13: return d_zf1;
        case 14: return d_zf2;
        case 15: return d_zf3;
    }
    return nullptr;
}

// ---------------- PTX helpers ----------------
typedef unsigned long long u64;

__device__ __forceinline__ uint32_t smem_u32(const void* p) {
    uint32_t a;
    asm("{ .reg .u64 t; cvta.to.shared.u64 t, %1; cvt.u32.u64 %0, t; }" : "=r"(a) : "l"(p));
    return a;
}
__device__ __forceinline__ void mma_bf16(float* d, const uint32_t* a, const uint32_t* b) {
    asm volatile(
        "mma.sync.aligned.m16n8k16.row.col.f32.bf16.bf16.f32 "
        "{%0,%1,%2,%3}, {%4,%5,%6,%7}, {%8,%9}, {%0,%1,%2,%3};"
        : "+f"(d[0]), "+f"(d[1]), "+f"(d[2]), "+f"(d[3])
        : "r"(a[0]), "r"(a[1]), "r"(a[2]), "r"(a[3]), "r"(b[0]), "r"(b[1]));
}
__device__ __forceinline__ void ldmx4(uint32_t* r, uint32_t addr) {
    asm volatile("ldmatrix.sync.aligned.m8n8.x4.shared.b16 {%0,%1,%2,%3}, [%4];"
                 : "=r"(r[0]), "=r"(r[1]), "=r"(r[2]), "=r"(r[3]) : "r"(addr));
}
__device__ __forceinline__ void cp16(uint32_t s, const void* g, int n) {
    asm volatile("cp.async.cg.shared.global [%0], [%1], 16, %2;"
                 :: "r"(s), "l"(g), "r"(n) : "memory");
}
#define CP_COMMIT() asm volatile("cp.async.commit_group;" ::: "memory")
#define CP_WAIT0()  asm volatile("cp.async.wait_group 0;" ::: "memory")
#define CP_WAIT1()  asm volatile("cp.async.wait_group 1;" ::: "memory")

// packed bf16 pair: hi halfword = bf16(x1), lo halfword = bf16(x0)  (RN, same as __float2bfloat16)
__device__ __forceinline__ uint32_t cvt_bf16x2(float x1, float x0) {
    uint32_t r;
    asm("cvt.rn.bf16x2.f32 %0, %1, %2;" : "=r"(r) : "f"(x1), "f"(x0));
    return r;
}

// split 8 floats into bf16 hi + lo packs (packed cvts; bit-identical to scalar path)
__device__ __forceinline__ void split8(const float* v, uint4& uh, uint4& ul) {
    uint32_t h[4], l[4];
#pragma unroll
    for (int j = 0; j < 4; j++) {
        float x0 = v[2 * j], x1 = v[2 * j + 1];
        uint32_t hp = cvt_bf16x2(x1, x0);
        float hf0 = __uint_as_float(hp << 16);
        float hf1 = __uint_as_float(hp & 0xffff0000u);
        l[j] = cvt_bf16x2(x1 - hf1, x0 - hf0);
        h[j] = hp;
    }
    uh = make_uint4(h[0], h[1], h[2], h[3]);
    ul = make_uint4(l[0], l[1], l[2], l[3]);
}
__device__ __forceinline__ uint4 cvt8(const float* v) {
    uint32_t h[4];
#pragma unroll
    for (int j = 0; j < 4; j++) h[j] = cvt_bf16x2(v[2 * j + 1], v[2 * j]);
    return make_uint4(h[0], h[1], h[2], h[3]);
}

__device__ __forceinline__ u64 splat2(float x) {
    u64 r; asm("mov.b64 %0, {%1, %1};" : "=l"(r) : "f"(x)); return r;
}
__device__ __forceinline__ void fma2(u64& d, u64 a, u64 b) {
    asm("fma.rn.f32x2 %0, %1, %2, %0;" : "+l"(d) : "l"(a), "l"(b));
}
__device__ __forceinline__ void unpack2(u64 p, float& lo, float& hi) {
    asm("mov.b64 {%0, %1}, %2;" : "=f"(lo), "=f"(hi) : "l"(p));
}
__device__ __forceinline__ void red4(float* addr, float4 v) {
    asm volatile("red.global.add.v4.f32 [%0], {%1,%2,%3,%4};"
                 :: "l"(addr), "f"(v.x), "f"(v.y), "f"(v.z), "f"(v.w) : "memory");
}

// ---------------- setup kernels ----------------
__global__ void k_zero_all() {
    int i = blockIdx.x * blockDim.x + threadIdx.x;
    int o = i;
    if (o < L_ * 1024) { d_stats[o] = 0.f; return; }
    o -= L_ * 1024;
    if (o < G_ * D_) { d_pool[o] = 0.f; return; }
    o -= G_ * D_;
    if (o < G_) { d_cnt[o] = 0.f; return; }
    o -= G_;
    if (o < N_) d_deg[o] = 0;
}

__global__ void k_hist(const int* __restrict__ ei) {
    int e = blockIdx.x * blockDim.x + threadIdx.x;
    if (e < E_) atomicAdd(&d_deg[ei[E_ + e]], 1);
}

__global__ void k_scan() {
    __shared__ int part[1024];
    int t = threadIdx.x;
    const int C = (N_ + 1023) / 1024;
    int lo = t * C, hi = min(lo + C, N_);
    int s = 0;
    for (int i = lo; i < hi; i++) s += d_deg[i];
    part[t] = s;
    __syncthreads();
    for (int off = 1; off < 1024; off <<= 1) {
        int v = (t >= off) ? part[t - off] : 0;
        __syncthreads();
        part[t] += v;
        __syncthreads();
    }
    int run = part[t] - s;
    for (int i = lo; i < hi; i++) {
        d_rowptr[i] = run;
        d_woff[i]   = run;
        run += d_deg[i];
    }
    if (t == 1023) d_rowptr[N_] = E_;
}

__global__ void k_scatter(const int* __restrict__ ei, const int* __restrict__ ea) {
    int e = blockIdx.x * blockDim.x + threadIdx.x;
    if (e >= E_) return;
    int dst = ei[E_ + e];
    int pos = atomicAdd(&d_woff[dst], 1);
    d_epack[pos] = make_int4(ei[e], ea[e * 3 + 0], ea[e * 3 + 1], ea[e * 3 + 2]);
}

// warp-per-node atom encoder
__global__ void k_atom(const int* __restrict__ x, const float* __restrict__ aemb) {
    int warp = (blockIdx.x * blockDim.x + threadIdx.x) >> 5;
    if (warp >= N_) return;
    int lane = threadIdx.x & 31;
    int d4 = lane * 4;
    float4 v = make_float4(0.f, 0.f, 0.f, 0.f);
#pragma unroll
    for (int f = 0; f < 9; f++) {
        int idx = x[warp * 9 + f];
        float4 t = *reinterpret_cast<const float4*>(aemb + ((size_t)f * V_ + idx) * D_ + d4);
        v.x += t.x; v.y += t.y; v.z += t.z; v.w += t.w;
    }
    *reinterpret_cast<float4*>(d_h + (size_t)warp * D_ + d4)    = v;
    *reinterpret_cast<float4*>(d_hsum + (size_t)warp * D_ + d4) = v;
}

// one edge message: relu(h(src) + bond(a0,a1,a2))
__device__ __forceinline__ float4 edge_msg(int4 ep, int d4, const float* __restrict__ bond,
                                           int useH, float4 sc, float4 sh) {
    float4 t0 = *reinterpret_cast<const float4*>(bond + ((size_t)0 * V_ + ep.y) * D_ + d4);
    float4 t1 = *reinterpret_cast<const float4*>(bond + ((size_t)1 * V_ + ep.z) * D_ + d4);
    float4 t2 = *reinterpret_cast<const float4*>(bond + ((size_t)2 * V_ + ep.w) * D_ + d4);
    float4 hv;
    if (useH) {
        hv = *reinterpret_cast<const float4*>(d_h + (size_t)ep.x * D_ + d4);
    } else {
        float4 pp = *reinterpret_cast<const float4*>(d_hpre + (size_t)ep.x * D_ + d4);
        hv.x = fmaxf(fmaf(pp.x, sc.x, sh.x), 0.f);
        hv.y = fmaxf(fmaf(pp.y, sc.y, sh.y), 0.f);
        hv.z = fmaxf(fmaf(pp.z, sc.z, sh.z), 0.f);
        hv.w = fmaxf(fmaf(pp.w, sc.w, sh.w), 0.f);
    }
    float4 m;
    m.x = fmaxf(hv.x + t0.x + t1.x + t2.x, 0.f);
    m.y = fmaxf(hv.y + t0.y + t1.y + t2.y, 0.f);
    m.z = fmaxf(hv.z + t0.z + t1.z + t2.z, 0.f);
    m.w = fmaxf(hv.w + t0.w + t1.w + t2.w, 0.f);
    return m;
}

// pull aggregation, fused prev-BN finalize + hsum update; pre-split bf16 out
__global__ void k_gather(const float* __restrict__ bond, const float* __restrict__ eps,
                         int l, int useH, int statOff, const float* __restrict__ g,
                         const float* __restrict__ b, float invM) {
    __shared__ float s_sc[D_], s_sh[D_];
    int tid = threadIdx.x;
    if (!useH) {
        if (tid < D_) {
            const float* st = d_stats + statOff;
            float mean = st[tid] * invM;
            float var  = st[D_ + tid] * invM - mean * mean;
            float is   = rsqrtf(var + 1e-5f);
            float sc   = g[tid] * is;
            s_sc[tid] = sc;
            s_sh[tid] = b[tid] - mean * sc;
        }
        __syncthreads();
    }

    int warp = (blockIdx.x * blockDim.x + tid) >> 5;
    if (warp >= N_) return;
    int lane = tid & 31;
    int d4 = lane * 4;

    float4 sc = make_float4(0.f, 0.f, 0.f, 0.f), sh = sc;
    if (!useH) {
        sc = *reinterpret_cast<const float4*>(s_sc + d4);
        sh = *reinterpret_cast<const float4*>(s_sh + d4);
    }

    float4 hd;
    if (useH) {
        hd = *reinterpret_cast<const float4*>(d_h + (size_t)warp * D_ + d4);
    } else {
        float4 p = *reinterpret_cast<const float4*>(d_hpre + (size_t)warp * D_ + d4);
        hd.x = fmaxf(fmaf(p.x, sc.x, sh.x), 0.f);
        hd.y = fmaxf(fmaf(p.y, sc.y, sh.y), 0.f);
        hd.z = fmaxf(fmaf(p.z, sc.z, sh.z), 0.f);
        hd.w = fmaxf(fmaf(p.w, sc.w, sh.w), 0.f);
        float4 hs = *reinterpret_cast<const float4*>(d_hsum + (size_t)warp * D_ + d4);
        hs.x += hd.x; hs.y += hd.y; hs.z += hd.z; hs.w += hd.w;
        *reinterpret_cast<float4*>(d_hsum + (size_t)warp * D_ + d4) = hs;
    }
    float s = 1.f + eps[l];
    float4 acc;
    acc.x = s * hd.x; acc.y = s * hd.y; acc.z = s * hd.z; acc.w = s * hd.w;

    int p0 = d_rowptr[warp], p1 = d_rowptr[warp + 1];
    int p = p0;
#pragma unroll 1
    for (; p + 2 <= p1; p += 2) {
        int4 e0 = d_epack[p];
        int4 e1 = d_epack[p + 1];
        float4 m0 = edge_msg(e0, d4, bond, useH, sc, sh);
        float4 m1 = edge_msg(e1, d4, bond, useH, sc, sh);
        acc.x += m0.x + m1.x;
        acc.y += m0.y + m1.y;
        acc.z += m0.z + m1.z;
        acc.w += m0.w + m1.w;
    }
    if (p < p1) {
        float4 m0 = edge_msg(d_epack[p], d4, bond, useH, sc, sh);
        acc.x += m0.x; acc.y += m0.y; acc.z += m0.z; acc.w += m0.w;
    }

    // split to bf16 hi/lo (packed cvts, bit-identical)
    uint32_t hp0 = cvt_bf16x2(acc.y, acc.x);
    uint32_t hp1 = cvt_bf16x2(acc.w, acc.z);
    float hf0 = __uint_as_float(hp0 << 16);
    float hf1 = __uint_as_float(hp0 & 0xffff0000u);
    float hf2 = __uint_as_float(hp1 << 16);
    float hf3 = __uint_as_float(hp1 & 0xffff0000u);
    uint32_t lp0 = cvt_bf16x2(acc.y - hf1, acc.x - hf0);
    uint32_t lp1 = cvt_bf16x2(acc.w - hf3, acc.z - hf2);
    *reinterpret_cast<uint2*>(d_Ah + (size_t)warp * D_ + d4) = make_uint2(hp0, hp1);
    *reinterpret_cast<uint2*>(d_Al + (size_t)warp * D_ + d4) = make_uint2(lp0, lp1);
}

// final layer: y = hpre*sc2+sh2 (no relu); hsum += y; pool hsum.
__global__ void k_apply_final(const int* __restrict__ batch, int statOff,
                              const float* __restrict__ g, const float* __restrict__ b,
                              float invM) {
    __shared__ float s_sc[D_], s_sh[D_];
    int tid = threadIdx.x;
    if (tid < D_) {
        const float* st = d_stats + statOff;
        float mean = st[tid] * invM;
        float var  = st[D_ + tid] * invM - mean * mean;
        float is   = rsqrtf(var + 1e-5f);
        float sc   = g[tid] * is;
        s_sc[tid] = sc;
        s_sh[tid] = b[tid] - mean * sc;
    }
    __syncthreads();

    int i = blockIdx.x * blockDim.x + tid;
    float4 p  = reinterpret_cast<const float4*>(d_hpre)[i];
    int c4 = i & 31;
    float4 sc = reinterpret_cast<const float4*>(s_sc)[c4];
    float4 sh = reinterpret_cast<const float4*>(s_sh)[c4];
    float4 y;
    y.x = fmaf(p.x, sc.x, sh.x);
    y.y = fmaf(p.y, sc.y, sh.y);
    y.z = fmaf(p.z, sc.z, sh.z);
    y.w = fmaf(p.w, sc.w, sh.w);
    float4 hs = reinterpret_cast<const float4*>(d_hsum)[i];
    hs.x += y.x; hs.y += y.y; hs.z += y.z; hs.w += y.w;
    int node = i >> 5;
    int q = i & 31;
    int gr = batch[node];
    red4(d_pool + (size_t)gr * D_ + q * 4, hs);
    if (q == 0) atomicAdd(&d_cnt[gr], 1.f);
}

__global__ void k_initbias(int id, const float* __restrict__ bias, int C, int n) {
    int i = blockIdx.x * blockDim.x + threadIdx.x;
    if (i < n) buf(id)[i] = bias[i % C];
}

__global__ void k_fc4(const float* __restrict__ w4, const float* __restrict__ b4,
                      float* __restrict__ out) {
    int g = blockIdx.x;
    int t = threadIdx.x;
    float acc = 0.f;
#pragma unroll
    for (int k = t; k < 512; k += 128)
        acc += fmaxf(d_zf3[(size_t)g * 512 + k], 0.f) * w4[k];
#pragma unroll
    for (int o = 16; o > 0; o >>= 1)
        acc += __shfl_down_sync(0xffffffffu, acc, o);
    __shared__ float sred[4];
    if ((t & 31) == 0) sred[t >> 5] = acc;
    __syncthreads();
    if (t == 0) out[g] = sred[0] + sred[1] + sred[2] + sred[3] + b4[0];
}

__global__ void k_cvtW2(const float* __restrict__ W1, const float* __restrict__ W2) {
    int idx = blockIdx.x * blockDim.x + threadIdx.x;
    const float* W; int K, Nc, wBase;
    if (idx < 4096)      { W = W1; K = 128; Nc = 256; wBase = 0; }
    else if (idx < 8192) { W = W2; K = 256; Nc = 128; wBase = 32768; idx -= 4096; }
    else return;
    int n  = idx / (K >> 3);
    int k0 = (idx % (K >> 3)) << 3;
    float v[8];
#pragma unroll
    for (int j = 0; j < 8; j++) v[j] = W[(size_t)(k0 + j) * Nc + n];
    uint4 uh = cvt8(v);
    size_t o = ((size_t)wBase + (size_t)n * K + k0) >> 3;
    reinterpret_cast<uint4*>(d_Wh)[o] = uh;
}

// ---------------- GEMM1: pre-split A, cp.async double-buffered (BM=128) ----
static constexpr int SSTR = 40;
static constexpr int TILE_B = 128 * SSTR * 2;
static constexpr int BUF_B  = 3 * TILE_B;
static constexpr int SMEM_PS = 2 * BUF_B;

__global__ __launch_bounds__(256, 2)
void k_mma_ps(int wBase, const float* __restrict__ bias, int cId,
              int M, int Nc, int K, int statOffOut) {
    extern __shared__ char smem_ps[];
    __shared__ float s_st[256];

    const int tid = threadIdx.x, lane = tid & 31, wid = tid >> 5;
    const int wm = wid >> 2, wn = wid & 3;
    const int mblk = blockIdx.y, nblk = blockIdx.x;
    const uint32_t sbase = smem_u32(smem_ps);

    float acc[4][4][4];
#pragma unroll
    for (int a = 0; a < 4; a++)
#pragma unroll
        for (int bq = 0; bq < 4; bq++)
#pragma unroll
            for (int c = 0; c < 4; c++) acc[a][bq][c] = 0.f;

    const int aoffb = ((lane & 15) * SSTR + ((lane >> 4) << 3)) * 2;
    const int piece = lane >> 3;
    const int boffb = (((lane & 7) + ((piece >> 1) << 3)) * SSTR + ((piece & 1) << 3)) * 2;

    const int nChunks = K >> 5;

    auto issue = [&](int kc, int bsel) {
        uint32_t aH = sbase + bsel * BUF_B;
        uint32_t aL = aH + TILE_B;
        uint32_t bH = aL + TILE_B;
#pragma unroll
        for (int it = 0; it < 2; it++) {
            int idx = it * 256 + tid;
            int r = idx >> 2;
            int c8 = (idx & 3) << 3;
            int soff = (r * SSTR + c8) * 2;
            int gr = mblk * 128 + r;
            int ok = (gr < M) ? 16 : 0;
            int grc = (gr < M) ? gr : (M - 1);
            size_t aoff = (size_t)grc * K + kc * 32 + c8;
            cp16(aH + soff, d_Ah + aoff, ok);
            cp16(aL + soff, d_Al + aoff, ok);
            cp16(bH + soff, d_Wh + wBase + (size_t)(nblk * 128 + r) * K + kc * 32 + c8, 16);
        }
        CP_COMMIT();
    };

    issue(0, 0);
    for (int kc = 0; kc < nChunks; kc++) {
        int bsel = kc & 1;
        if (kc + 1 < nChunks) {
            issue(kc + 1, bsel ^ 1);
            CP_WAIT1();
        } else {
            CP_WAIT0();
        }
        __syncthreads();

        uint32_t aH = sbase + bsel * BUF_B;
        uint32_t aL = aH + TILE_B;
        uint32_t bH = aL + TILE_B;
#pragma unroll
        for (int ks = 0; ks < 2; ks++) {
            const int kb = ks * 32;
            uint32_t a_h[4][4], a_l[4][4], b_h[4][2];
#pragma unroll
            for (int mi = 0; mi < 4; mi++) {
                int off = aoffb + kb + (wm * 64 + mi * 16) * (SSTR * 2);
                ldmx4(a_h[mi], aH + off);
                ldmx4(a_l[mi], aL + off);
            }
#pragma unroll
            for (int nj = 0; nj < 2; nj++) {
                int off = boffb + kb + (wn * 32 + nj * 16) * (SSTR * 2);
                uint32_t r4[4];
                ldmx4(r4, bH + off);
                b_h[nj * 2][0] = r4[0]; b_h[nj * 2][1] = r4[1];
                b_h[nj * 2 + 1][0] = r4[2]; b_h[nj * 2 + 1][1] = r4[3];
            }
#pragma unroll
            for (int mi = 0; mi < 4; mi++)
#pragma unroll
                for (int ni = 0; ni < 4; ni++) {
                    mma_bf16(acc[mi][ni], a_h[mi], b_h[ni]);
                    mma_bf16(acc[mi][ni], a_l[mi], b_h[ni]);
                }
        }
        __syncthreads();
    }

    float* C = buf(cId);
    float st_s[8], st_q[8];
#pragma unroll
    for (int j = 0; j < 8; j++) { st_s[j] = 0.f; st_q[j] = 0.f; }

#pragma unroll
    for (int mi = 0; mi < 4; mi++) {
        int row0 = mblk * 128 + wm * 64 + mi * 16 + (lane >> 2);
#pragma unroll
        for (int ni = 0; ni < 4; ni++) {
            int col = nblk * 128 + wn * 32 + ni * 8 + ((lane & 3) << 1);
            float b0 = bias[col], b1 = bias[col + 1];
            float v0 = acc[mi][ni][0] + b0, v1 = acc[mi][ni][1] + b1;
            float v2 = acc[mi][ni][2] + b0, v3 = acc[mi][ni][3] + b1;
            if (row0 < M) {
                *reinterpret_cast<float2*>(&C[(size_t)row0 * Nc + col]) = make_float2(v0, v1);
                st_s[ni * 2]     += v0; st_q[ni * 2]     += v0 * v0;
                st_s[ni * 2 + 1] += v1; st_q[ni * 2 + 1] += v1 * v1;
            }
            if (row0 + 8 < M) {
                *reinterpret_cast<float2*>(&C[(size_t)(row0 + 8) * Nc + col]) = make_float2(v2, v3);
                st_s[ni * 2]     += v2; st_q[ni * 2]     += v2 * v2;
                st_s[ni * 2 + 1] += v3; st_q[ni * 2 + 1] += v3 * v3;
            }
        }
    }

    __syncthreads();
    s_st[tid] = 0.f;
    __syncthreads();
#pragma unroll
    for (int j = 0; j < 8; j++) {
        int colLocal = wn * 32 + (j >> 1) * 8 + ((lane & 3) << 1) + (j & 1);
        atomicAdd(&s_st[colLocal], st_s[j]);
        atomicAdd(&s_st[128 + colLocal], st_q[j]);
    }
    __syncthreads();
    if (tid < 128) {
        atomicAdd(&d_stats[statOffOut + nblk * 128 + tid], s_st[tid]);
        atomicAdd(&d_stats[statOffOut + Nc + nblk * 128 + tid], s_st[128 + tid]);
    }
}

// ---------------- GEMM2: BM=128, pipelined B (cp.async), hoisted A LDG -----
__global__ __launch_bounds__(256, 2)
void k_mma2(int aId, int wBase, const float* __restrict__ bias, int cId,
            int M, int Nc, int K, int statOffOut,
            int statOffIn, const float* __restrict__ g, const float* __restrict__ b,
            float invM) {
    __shared__ __nv_bfloat16 As_h[128 * SSTR];
    __shared__ __nv_bfloat16 As_l[128 * SSTR];
    __shared__ __nv_bfloat16 Bs_h[2][128 * SSTR];
    __shared__ float s_st[256];
    __shared__ float s_sc1[256], s_sh1[256];

    const float* A = buf(aId);
    const int tid = threadIdx.x, lane = tid & 31, wid = tid >> 5;
    const int wm = wid >> 2, wn = wid & 3;
    const int mblk = blockIdx.y, nblk = blockIdx.x;

    // fused finalize of previous BN (K = 256, blockDim = 256)
    if (tid < K) {
        const float* st = d_stats + statOffIn;
        float mean = st[tid] * invM;
        float var  = st[K + tid] * invM - mean * mean;
        float is   = rsqrtf(var + 1e-5f);
        float sc   = g[tid] * is;
        s_sc1[tid] = sc;
        s_sh1[tid] = b[tid] - mean * sc;
    }

    float acc[4][4][4];
#pragma unroll
    for (int a = 0; a < 4; a++)
#pragma unroll
        for (int bq = 0; bq < 4; bq++)
#pragma unroll
            for (int c = 0; c < 4; c++) acc[a][bq][c] = 0.f;

    const uint32_t sAh = smem_u32(As_h), sAl = smem_u32(As_l);
    const uint32_t sB0 = smem_u32(Bs_h);

    const int aoffb = ((lane & 15) * SSTR + ((lane >> 4) << 3)) * 2;
    const int piece = lane >> 3;
    const int boffb = (((lane & 7) + ((piece >> 1) << 3)) * SSTR + ((piece & 1) << 3)) * 2;

    const int nChunks = K >> 5;

    auto issueB = [&](int kc, int bsel) {
        uint32_t bH = sB0 + bsel * (uint32_t)(128 * SSTR * 2);
#pragma unroll
        for (int it = 0; it < 2; it++) {
            int idx = it * 256 + tid;
            int r = idx >> 2;
            int c8 = (idx & 3) << 3;
            cp16(bH + (uint32_t)(r * SSTR + c8) * 2,
                 d_Wh + wBase + (size_t)(nblk * 128 + r) * K + kc * 32 + c8, 16);
        }
        CP_COMMIT();
    };

    issueB(0, 0);
    __syncthreads();    // also covers s_sc1/s_sh1 init visibility

    for (int kc = 0; kc < nChunks; kc++) {
        int bsel = kc & 1;

        // hoist A fp32 loads (latency overlaps B prefetch + transform)
        float v[2][8];
        int sof[2];
#pragma unroll
        for (int it = 0; it < 2; it++) {
            int idx = it * 256 + tid;
            int r = idx >> 2;
            int c8 = (idx & 3) << 3;
            int gr = mblk * 128 + r;
            int gc = kc * 32 + c8;
            sof[it] = r * SSTR + c8;
#pragma unroll
            for (int j = 0; j < 8; j++) v[it][j] = 0.f;
            if (gr < M) {
                const float4* s = reinterpret_cast<const float4*>(A + (size_t)gr * K + gc);
                *reinterpret_cast<float4*>(v[it])     = s[0];
                *reinterpret_cast<float4*>(v[it] + 4) = s[1];
            }
        }
        if (kc + 1 < nChunks) issueB(kc + 1, bsel ^ 1);

        // transform + split + store A (prev mma done: trailing sync of last iter)
#pragma unroll
        for (int it = 0; it < 2; it++) {
            int idx = it * 256 + tid;
            int gc = kc * 32 + ((idx & 3) << 3);
#pragma unroll
            for (int j = 0; j < 8; j++)
                v[it][j] = fmaxf(fmaf(v[it][j], s_sc1[gc + j], s_sh1[gc + j]), 0.f);
            uint4 uh, ul;
            split8(v[it], uh, ul);
            *reinterpret_cast<uint4*>(&As_h[sof[it]]) = uh;
            *reinterpret_cast<uint4*>(&As_l[sof[it]]) = ul;
        }

        if (kc + 1 < nChunks) CP_WAIT1(); else CP_WAIT0();
        __syncthreads();

        uint32_t bH = sB0 + bsel * (uint32_t)(128 * SSTR * 2);
#pragma unroll
        for (int ks = 0; ks < 2; ks++) {
            const int kb = ks * 32;
            uint32_t a_h[4][4], a_l[4][4], b_h[4][2];
#pragma unroll
            for (int mi = 0; mi < 4; mi++) {
                int off = aoffb + kb + (wm * 64 + mi * 16) * (SSTR * 2);
                ldmx4(a_h[mi], sAh + off);
                ldmx4(a_l[mi], sAl + off);
            }
#pragma unroll
            for (int nj = 0; nj < 2; nj++) {
                int off = boffb + kb + (wn * 32 + nj * 16) * (SSTR * 2);
                uint32_t r4[4];
                ldmx4(r4, bH + off);
                b_h[nj * 2][0] = r4[0]; b_h[nj * 2][1] = r4[1];
                b_h[nj * 2 + 1][0] = r4[2]; b_h[nj * 2 + 1][1] = r4[3];
            }
#pragma unroll
            for (int mi = 0; mi < 4; mi++)
#pragma unroll
                for (int ni = 0; ni < 4; ni++) {
                    mma_bf16(acc[mi][ni], a_h[mi], b_h[ni]);
                    mma_bf16(acc[mi][ni], a_l[mi], b_h[ni]);
                }
        }
        __syncthreads();
    }

    float* C = buf(cId);
    float st_s[8], st_q[8];
#pragma unroll
    for (int j = 0; j < 8; j++) { st_s[j] = 0.f; st_q[j] = 0.f; }

#pragma unroll
    for (int mi = 0; mi < 4; mi++) {
        int row0 = mblk * 128 + wm * 64 + mi * 16 + (lane >> 2);
#pragma unroll
        for (int ni = 0; ni < 4; ni++) {
            int col = nblk * 128 + wn * 32 + ni * 8 + ((lane & 3) << 1);
            float b0 = bias[col], b1 = bias[col + 1];
            float v0 = acc[mi][ni][0] + b0, v1 = acc[mi][ni][1] + b1;
            float v2 = acc[mi][ni][2] + b0, v3 = acc[mi][ni][3] + b1;
            if (row0 < M) {
                *reinterpret_cast<float2*>(&C[(size_t)row0 * Nc + col]) = make_float2(v0, v1);
                st_s[ni * 2]     += v0; st_q[ni * 2]     += v0 * v0;
                st_s[ni * 2 + 1] += v1; st_q[ni * 2 + 1] += v1 * v1;
            }
            if (row0 + 8 < M) {
                *reinterpret_cast<float2*>(&C[(size_t)(row0 + 8) * Nc + col]) = make_float2(v2, v3);
                st_s[ni * 2]     += v2; st_q[ni * 2]     += v2 * v2;
                st_s[ni * 2 + 1] += v3; st_q[ni * 2 + 1] += v3 * v3;
            }
        }
    }

    __syncthreads();
    s_st[tid] = 0.f;
    __syncthreads();
#pragma unroll
    for (int j = 0; j < 8; j++) {
        int colLocal = wn * 32 + (j >> 1) * 8 + ((lane & 3) << 1) + (j & 1);
        atomicAdd(&s_st[colLocal], st_s[j]);
        atomicAdd(&s_st[128 + colLocal], st_q[j]);
    }
    __syncthreads();
    if (tid < 128) {
        atomicAdd(&d_stats[statOffOut + nblk * 128 + tid], s_st[tid]);
        atomicAdd(&d_stats[statOffOut + Nc + nblk * 128 + tid], s_st[128 + tid]);
    }
}

// ---------------- FFMA2 SGEMM (FC head only) ----------------
// XF: 0 none, 1 relu, 3 pool/max(cnt,1)  (fc1 reads pooled sums directly)
template <int BM, int BN, int BK, int TM, int TN, int XF, bool ATOMIC>
__launch_bounds__((BM / TM) * (BN / TN))
__global__ void k_sgemm(int aId, const float* __restrict__ W,
                        const float* __restrict__ bias, int cId,
                        int M, int K, int Nc, int kLen) {
    constexpr int THREADS = (BM / TM) * (BN / TN);
    constexpr int PAD = 4;
    __shared__ float As[BK][BM + PAD];
    __shared__ float Ws[BK][BN];

    const float* A = (XF == 3) ? d_pool : buf(aId);
    float* C = buf(cId);

    const int tid  = threadIdx.x;
    const int tcol = tid % (BN / TN);
    const int trow = tid / (BN / TN);
    const int rowBase = blockIdx.y * BM;
    const int colBase = blockIdx.x * BN;
    const int kStart  = blockIdx.z * kLen;

    u64 acc2[TM / 2][TN];
#pragma unroll
    for (int i = 0; i < TM / 2; i++)
#pragma unroll
        for (int j = 0; j < TN; j++) acc2[i][j] = 0ull;

    constexpr int AROWS_PER   = (BM * BK) / THREADS;
    constexpr int AROW_STRIDE = THREADS / BK;
    constexpr int WROWS_PER   = (BK * BN) / THREADS;
    constexpr int WROW_STRIDE = THREADS / BN;

    const int aCol = tid % BK;
    const int aRow = tid / BK;
    const int wCol = tid % BN;
    const int wRow = tid / BN;

    for (int k0 = kStart; k0 < kStart + kLen; k0 += BK) {
        const int kk = k0 + aCol;
#pragma unroll
        for (int r = 0; r < AROWS_PER; r++) {
            int row = rowBase + aRow + r * AROW_STRIDE;
            float v = (row < M) ? A[(size_t)row * K + kk] : 0.f;
            if (XF == 1) v = fmaxf(v, 0.f);
            if (XF == 3 && row < M) v = v / fmaxf(d_cnt[row], 1.f);
            As[aCol][aRow + r * AROW_STRIDE] = v;
        }
#pragma unroll
        for (int r = 0; r < WROWS_PER; r++) {
            Ws[wRow + r * WROW_STRIDE][wCol] =
                W[(size_t)(k0 + wRow + r * WROW_STRIDE) * Nc + colBase + wCol];
        }
        __syncthreads();
#pragma unroll
        for (int kq = 0; kq < BK; kq++) {
            u64 a2[TM / 2];
            const u64* ap = reinterpret_cast<const u64*>(&As[kq][trow * TM]);
#pragma unroll
            for (int i = 0; i < TM / 2; i++) a2[i] = ap[i];
            float4 wv = *reinterpret_cast<const float4*>(&Ws[kq][tcol * TN]);
            float wf[4] = {wv.x, wv.y, wv.z, wv.w};
#pragma unroll
            for (int j = 0; j < TN; j++) {
                u64 wp = splat2(wf[j]);
#pragma unroll
                for (int i = 0; i < TM / 2; i++) fma2(acc2[i][j], a2[i], wp);
            }
        }
        __syncthreads();
    }

#pragma unroll
    for (int i = 0; i < TM / 2; i++) {
        int row0 = rowBase + trow * TM + 2 * i;
        float lo[TN], hi[TN];
#pragma unroll
        for (int j = 0; j < TN; j++) unpack2(acc2[i][j], lo[j], hi[j]);
        int col0 = colBase + tcol * TN;
        if (ATOMIC) {
            if (row0 < M) {
#pragma unroll
                for (int j = 0; j < TN; j++) atomicAdd(&C[(size_t)row0 * Nc + col0 + j], lo[j]);
            }
            if (row0 + 1 < M) {
#pragma unroll
                for (int j = 0; j < TN; j++) atomicAdd(&C[(size_t)(row0 + 1) * Nc + col0 + j], hi[j]);
            }
        } else {
            float bc[TN];
#pragma unroll
            for (int j = 0; j < TN; j++) bc[j] = bias[col0 + j];
            if (row0 < M) {
#pragma unroll
                for (int j = 0; j < TN; j++) C[(size_t)row0 * Nc + col0 + j] = lo[j] + bc[j];
            }
            if (row0 + 1 < M) {
#pragma unroll
                for (int j = 0; j < TN; j++) C[(size_t)(row0 + 1) * Nc + col0 + j] = hi[j] + bc[j];
            }
        }
    }
}

// ---------------- launch ----------------
extern "C" void kernel_launch(void* const* d_in, const int* in_sizes, int n_in,
                              void* d_out, int out_size) {
    const int*   x        = (const int*)  d_in[0];
    const int*   ei       = (const int*)  d_in[1];
    const int*   ea       = (const int*)  d_in[2];
    const int*   batch    = (const int*)  d_in[3];
    const float* atom_emb = (const float*)d_in[4];
    const float* bond_emb = (const float*)d_in[5];
    const float* eps      = (const float*)d_in[6];
    const float* W1       = (const float*)d_in[7];
    const float* b1       = (const float*)d_in[8];
    const float* g1       = (const float*)d_in[9];
    const float* be1      = (const float*)d_in[10];
    const float* W2       = (const float*)d_in[11];
    const float* b2       = (const float*)d_in[12];
    const float* bn_g     = (const float*)d_in[13];
    const float* bn_b     = (const float*)d_in[14];
    const float* fcW1     = (const float*)d_in[15];
    const float* fcb1     = (const float*)d_in[16];
    const float* fcW2     = (const float*)d_in[17];
    const float* fcb2     = (const float*)d_in[18];
    const float* fcW3     = (const float*)d_in[19];
    const float* fcb3     = (const float*)d_in[20];
    const float* fcW4     = (const float*)d_in[21];
    const float* fcb4     = (const float*)d_in[22];
    float* out = (float*)d_out;

    const float invN = 1.f / (float)N_;

    static bool attrSet = false;
    if (!attrSet) {
        cudaFuncSetAttribute(k_mma_ps, cudaFuncAttributeMaxDynamicSharedMemorySize, SMEM_PS);
        attrSet = true;
    }

    // setup + CSR build
    k_zero_all<<<(L_ * 1024 + G_ * D_ + G_ + N_ + 255) / 256, 256>>>();
    k_cvtW2<<<(8192 + 255) / 256, 256>>>(W1, W2);
    k_atom<<<(N_ * 32 + 255) / 256, 256>>>(x, atom_emb);
    k_hist<<<(E_ + 255) / 256, 256>>>(ei);
    k_scan<<<1, 1024>>>();
    k_scatter<<<(E_ + 255) / 256, 256>>>(ei, ea);

    for (int l = 0; l < L_; l++) {
        // gather: fused prev-BN finalize + hsum + pull aggregation; bf16 split out
        k_gather<<<(N_ * 32 + 255) / 256, 256>>>(bond_emb + (size_t)l * 3 * V_ * D_,
                                                 eps, l, l == 0 ? 1 : 0,
                                                 (l - 1) * 1024 + 512,
                                                 bn_g + (l - 1) * D_, bn_b + (l - 1) * D_,
                                                 invN);

        // GEMM1: z1 = (Ah+Al) @ W1 + b1, cp.async double-buffered, fused stats
        k_mma_ps<<<dim3(2, MBLKS), 256, SMEM_PS>>>(0, b1, 3, N_, 256, 128, l * 1024);

        // GEMM2 (pipelined): hpre = relu(bn1(z1)) @ W2 + b2, bn1 finalize fused
        k_mma2<<<dim3(1, MBLKS), 256>>>(3, 32768, b2, 4, N_, 128, 256,
                                        l * 1024 + 512, l * 1024, g1, be1, invN);
    }

    // final layer: y (no relu) + hsum + pool
    k_apply_final<<<(N_ * 32) / 256, 256>>>(batch, (L_ - 1) * 1024 + 512,
                                            bn_g + (L_ - 1) * D_, bn_b + (L_ - 1) * D_, invN);

    // FC head (fc1 reads pool/cnt directly; k_rep eliminated)
    k_sgemm<64, 64, 16, 4, 4, 3, false>
        <<<dim3(1024 / 64, G_ / 64, 1), 256>>>(10, fcW1, fcb1, 13, G_, 128, 1024, 128);

    k_initbias<<<(G_ * 1024) / 256, 256>>>(14, fcb2, 1024, G_ * 1024);
    k_sgemm<64, 64, 16, 4, 4, 1, true>
        <<<dim3(1024 / 64, G_ / 64, 8), 256>>>(13, fcW2, nullptr, 14, G_, 1024, 1024, 128);

    k_initbias<<<(G_ * 512) / 256, 256>>>(15, fcb3, 512, G_ * 512);
    k_sgemm<64, 64, 16, 4, 4, 1, true>
        <<<dim3(512 / 64, G_ / 64, 8), 256>>>(14, fcW3, nullptr, 15, G_, 1024, 512, 128);

    k_fc4<<<G_, 128>>>(fcW4, fcb4, out);
}

// round 17
// speedup vs baseline: 1.0671x; 1.0671x over previous
#include <cuda_runtime.h>
#include <cuda_bf16.h>
#include <cstdint>

// ---------------- problem constants ----------------
static constexpr int N_ = 50000;
static constexpr int E_ = 600000;
static constexpr int G_ = 256;
static constexpr int D_ = 128;
static constexpr int L_ = 5;
static constexpr int V_ = 128;

static constexpr int MBLKS = (N_ + 127) / 128;   // 391
static constexpr int BONDE = L_ * 3 * V_ * D_;   // 245760 elems

// ---------------- scratch (static device globals; no runtime alloc) --------
__device__ float d_h   [N_ * D_];
__device__ float d_hsum[N_ * D_];
__device__ float d_z1  [N_ * 2 * D_];
__device__ float d_hpre[N_ * D_];
__device__ float d_stats[L_ * 1024];
__device__ float d_pool[G_ * D_];
__device__ float d_cnt [G_];
__device__ float d_zf1 [G_ * 1024];
__device__ float d_zf2 [G_ * 1024];
__device__ float d_zf3 [G_ * 512];

// pre-split GEMM1 A operand (written by k_gather)
__device__ __nv_bfloat16 d_Ah[N_ * D_];
__device__ __nv_bfloat16 d_Al[N_ * D_];

// bf16 bond tables (all layers; 491KB, L1/L2 resident)
__device__ __nv_bfloat16 d_bond[BONDE];

// CSR edge structures
__device__ int  d_deg   [N_];
__device__ int  d_rowptr[N_ + 1];
__device__ int  d_woff  [N_];
__device__ int4 d_epack [E_];

// bf16 weights (row-major W^T)
__device__ __nv_bfloat16 d_Wh[65536];   // W1^T [256,128] @0, W2^T [128,256] @32768

__device__ __forceinline__ float* buf(int id) {
    switch (id) {
        case 0:  return d_h;
        case 1:  return d_hsum;
        case 3:  return d_z1;
        case 4:  return d_hpre;
        case 5:  return d_stats;
        case 10: return d_pool;
        case 11: return d_cnt;
        case 13: return d_zf1;
        case 14: return d_zf2;
        case 15: return d_zf3;
    }
    return nullptr;
}

// ---------------- PTX helpers ----------------
typedef unsigned long long u64;

__device__ __forceinline__ uint32_t smem_u32(const void* p) {
    uint32_t a;
    asm("{ .reg .u64 t; cvta.to.shared.u64 t, %1; cvt.u32.u64 %0, t; }" : "=r"(a) : "l"(p));
    return a;
}
__device__ __forceinline__ void mma_bf16(float* d, const uint32_t* a, const uint32_t* b) {
    asm volatile(
        "mma.sync.aligned.m16n8k16.row.col.f32.bf16.bf16.f32 "
        "{%0,%1,%2,%3}, {%4,%5,%6,%7}, {%8,%9}, {%0,%1,%2,%3};"
        : "+f"(d[0]), "+f"(d[1]), "+f"(d[2]), "+f"(d[3])
        : "r"(a[0]), "r"(a[1]), "r"(a[2]), "r"(a[3]), "r"(b[0]), "r"(b[1]));
}
__device__ __forceinline__ void ldmx4(uint32_t* r, uint32_t addr) {
    asm volatile("ldmatrix.sync.aligned.m8n8.x4.shared.b16 {%0,%1,%2,%3}, [%4];"
                 : "=r"(r[0]), "=r"(r[1]), "=r"(r[2]), "=r"(r[3]) : "r"(addr));
}
__device__ __forceinline__ void cp16(uint32_t s, const void* g, int n) {
    asm volatile("cp.async.cg.shared.global [%0], [%1], 16, %2;"
                 :: "r"(s), "l"(g), "r"(n) : "memory");
}
#define CP_COMMIT() asm volatile("cp.async.commit_group;" ::: "memory")
#define CP_WAIT0()  asm volatile("cp.async.wait_group 0;" ::: "memory")
#define CP_WAIT1()  asm volatile("cp.async.wait_group 1;" ::: "memory")

__device__ __forceinline__ uint32_t cvt_bf16x2(float x1, float x0) {
    uint32_t r;
    asm("cvt.rn.bf16x2.f32 %0, %1, %2;" : "=r"(r) : "f"(x1), "f"(x0));
    return r;
}

// split 8 floats into bf16 hi + lo packs (packed cvts)
__device__ __forceinline__ void split8(const float* v, uint4& uh, uint4& ul) {
    uint32_t h[4], l[4];
#pragma unroll
    for (int j = 0; j < 4; j++) {
        float x0 = v[2 * j], x1 = v[2 * j + 1];
        uint32_t hp = cvt_bf16x2(x1, x0);
        float hf0 = __uint_as_float(hp << 16);
        float hf1 = __uint_as_float(hp & 0xffff0000u);
        l[j] = cvt_bf16x2(x1 - hf1, x0 - hf0);
        h[j] = hp;
    }
    uh = make_uint4(h[0], h[1], h[2], h[3]);
    ul = make_uint4(l[0], l[1], l[2], l[3]);
}
__device__ __forceinline__ uint4 cvt8(const float* v) {
    uint32_t h[4];
#pragma unroll
    for (int j = 0; j < 4; j++) h[j] = cvt_bf16x2(v[2 * j + 1], v[2 * j]);
    return make_uint4(h[0], h[1], h[2], h[3]);
}

// load 4 bf16 as fp32 (exact upconvert via shifts)
__device__ __forceinline__ float4 ldbf4(const __nv_bfloat16* p) {
    uint2 u = *reinterpret_cast<const uint2*>(p);
    float4 r;
    r.x = __uint_as_float(u.x << 16);
    r.y = __uint_as_float(u.x & 0xffff0000u);
    r.z = __uint_as_float(u.y << 16);
    r.w = __uint_as_float(u.y & 0xffff0000u);
    return r;
}

__device__ __forceinline__ u64 splat2(float x) {
    u64 r; asm("mov.b64 %0, {%1, %1};" : "=l"(r) : "f"(x)); return r;
}
__device__ __forceinline__ void fma2(u64& d, u64 a, u64 b) {
    asm("fma.rn.f32x2 %0, %1, %2, %0;" : "+l"(d) : "l"(a), "l"(b));
}
__device__ __forceinline__ void unpack2(u64 p, float& lo, float& hi) {
    asm("mov.b64 {%0, %1}, %2;" : "=f"(lo), "=f"(hi) : "l"(p));
}
__device__ __forceinline__ void red4(float* addr, float4 v) {
    asm volatile("red.global.add.v4.f32 [%0], {%1,%2,%3,%4};"
                 :: "l"(addr), "f"(v.x), "f"(v.y), "f"(v.z), "f"(v.w) : "memory");
}

// ---------------- setup kernels ----------------
__global__ void k_zero_all() {
    int i = blockIdx.x * blockDim.x + threadIdx.x;
    int o = i;
    if (o < L_ * 1024) { d_stats[o] = 0.f; return; }
    o -= L_ * 1024;
    if (o < G_ * D_) { d_pool[o] = 0.f; return; }
    o -= G_ * D_;
    if (o < G_) { d_cnt[o] = 0.f; return; }
    o -= G_;
    if (o < N_) d_deg[o] = 0;
}

__global__ void k_hist(const int* __restrict__ ei) {
    int e = blockIdx.x * blockDim.x + threadIdx.x;
    if (e < E_) atomicAdd(&d_deg[ei[E_ + e]], 1);
}

__global__ void k_scan() {
    __shared__ int part[1024];
    int t = threadIdx.x;
    const int C = (N_ + 1023) / 1024;
    int lo = t * C, hi = min(lo + C, N_);
    int s = 0;
    for (int i = lo; i < hi; i++) s += d_deg[i];
    part[t] = s;
    __syncthreads();
    for (int off = 1; off < 1024; off <<= 1) {
        int v = (t >= off) ? part[t - off] : 0;
        __syncthreads();
        part[t] += v;
        __syncthreads();
    }
    int run = part[t] - s;
    for (int i = lo; i < hi; i++) {
        d_rowptr[i] = run;
        d_woff[i]   = run;
        run += d_deg[i];
    }
    if (t == 1023) d_rowptr[N_] = E_;
}

__global__ void k_scatter(const int* __restrict__ ei, const int* __restrict__ ea) {
    int e = blockIdx.x * blockDim.x + threadIdx.x;
    if (e >= E_) return;
    int dst = ei[E_ + e];
    int pos = atomicAdd(&d_woff[dst], 1);
    d_epack[pos] = make_int4(ei[e], ea[e * 3 + 0], ea[e * 3 + 1], ea[e * 3 + 2]);
}

// convert all bond tables to bf16 once per call
__global__ void k_cvtBond(const float* __restrict__ bond) {
    int i = blockIdx.x * blockDim.x + threadIdx.x;   // 8 elems per thread
    if (i >= BONDE / 8) return;
    float v[8];
    const float4* s = reinterpret_cast<const float4*>(bond + (size_t)i * 8);
    *reinterpret_cast<float4*>(v)     = s[0];
    *reinterpret_cast<float4*>(v + 4) = s[1];
    reinterpret_cast<uint4*>(d_bond)[i] = cvt8(v);
}

// warp-per-node atom encoder
__global__ void k_atom(const int* __restrict__ x, const float* __restrict__ aemb) {
    int warp = (blockIdx.x * blockDim.x + threadIdx.x) >> 5;
    if (warp >= N_) return;
    int lane = threadIdx.x & 31;
    int d4 = lane * 4;
    float4 v = make_float4(0.f, 0.f, 0.f, 0.f);
#pragma unroll
    for (int f = 0; f < 9; f++) {
        int idx = x[warp * 9 + f];
        float4 t = *reinterpret_cast<const float4*>(aemb + ((size_t)f * V_ + idx) * D_ + d4);
        v.x += t.x; v.y += t.y; v.z += t.z; v.w += t.w;
    }
    *reinterpret_cast<float4*>(d_h + (size_t)warp * D_ + d4)    = v;
    *reinterpret_cast<float4*>(d_hsum + (size_t)warp * D_ + d4) = v;
}

// one edge message: relu(h(src) + bond_bf16(a0,a1,a2))
__device__ __forceinline__ float4 edge_msg(int4 ep, int d4, const __nv_bfloat16* bond,
                                           int useH, float4 sc, float4 sh) {
    float4 t0 = ldbf4(bond + ((size_t)0 * V_ + ep.y) * D_ + d4);
    float4 t1 = ldbf4(bond + ((size_t)1 * V_ + ep.z) * D_ + d4);
    float4 t2 = ldbf4(bond + ((size_t)2 * V_ + ep.w) * D_ + d4);
    float4 hv;
    if (useH) {
        hv = *reinterpret_cast<const float4*>(d_h + (size_t)ep.x * D_ + d4);
    } else {
        float4 pp = *reinterpret_cast<const float4*>(d_hpre + (size_t)ep.x * D_ + d4);
        hv.x = fmaxf(fmaf(pp.x, sc.x, sh.x), 0.f);
        hv.y = fmaxf(fmaf(pp.y, sc.y, sh.y), 0.f);
        hv.z = fmaxf(fmaf(pp.z, sc.z, sh.z), 0.f);
        hv.w = fmaxf(fmaf(pp.w, sc.w, sh.w), 0.f);
    }
    float4 m;
    m.x = fmaxf(hv.x + t0.x + t1.x + t2.x, 0.f);
    m.y = fmaxf(hv.y + t0.y + t1.y + t2.y, 0.f);
    m.z = fmaxf(hv.z + t0.z + t1.z + t2.z, 0.f);
    m.w = fmaxf(hv.w + t0.w + t1.w + t2.w, 0.f);
    return m;
}

// pull aggregation, fused prev-BN finalize + hsum update; pre-split bf16 out
__global__ void k_gather(int bondOff, const float* __restrict__ eps,
                         int l, int useH, int statOff, const float* __restrict__ g,
                         const float* __restrict__ b, float invM) {
    __shared__ float s_sc[D_], s_sh[D_];
    int tid = threadIdx.x;
    if (!useH) {
        if (tid < D_) {
            const float* st = d_stats + statOff;
            float mean = st[tid] * invM;
            float var  = st[D_ + tid] * invM - mean * mean;
            float is   = rsqrtf(var + 1e-5f);
            float sc   = g[tid] * is;
            s_sc[tid] = sc;
            s_sh[tid] = b[tid] - mean * sc;
        }
        __syncthreads();
    }

    const __nv_bfloat16* bond = d_bond + bondOff;
    int warp = (blockIdx.x * blockDim.x + tid) >> 5;
    if (warp >= N_) return;
    int lane = tid & 31;
    int d4 = lane * 4;

    float4 sc = make_float4(0.f, 0.f, 0.f, 0.f), sh = sc;
    if (!useH) {
        sc = *reinterpret_cast<const float4*>(s_sc + d4);
        sh = *reinterpret_cast<const float4*>(s_sh + d4);
    }

    float4 hd;
    if (useH) {
        hd = *reinterpret_cast<const float4*>(d_h + (size_t)warp * D_ + d4);
    } else {
        float4 p = *reinterpret_cast<const float4*>(d_hpre + (size_t)warp * D_ + d4);
        hd.x = fmaxf(fmaf(p.x, sc.x, sh.x), 0.f);
        hd.y = fmaxf(fmaf(p.y, sc.y, sh.y), 0.f);
        hd.z = fmaxf(fmaf(p.z, sc.z, sh.z), 0.f);
        hd.w = fmaxf(fmaf(p.w, sc.w, sh.w), 0.f);
        float4 hs = *reinterpret_cast<const float4*>(d_hsum + (size_t)warp * D_ + d4);
        hs.x += hd.x; hs.y += hd.y; hs.z += hd.z; hs.w += hd.w;
        *reinterpret_cast<float4*>(d_hsum + (size_t)warp * D_ + d4) = hs;
    }
    float s = 1.f + eps[l];
    float4 acc;
    acc.x = s * hd.x; acc.y = s * hd.y; acc.z = s * hd.z; acc.w = s * hd.w;

    int p0 = d_rowptr[warp], p1 = d_rowptr[warp + 1];
    int p = p0;
#pragma unroll 1
    for (; p + 2 <= p1; p += 2) {
        int4 e0 = d_epack[p];
        int4 e1 = d_epack[p + 1];
        float4 m0 = edge_msg(e0, d4, bond, useH, sc, sh);
        float4 m1 = edge_msg(e1, d4, bond, useH, sc, sh);
        acc.x += m0.x + m1.x;
        acc.y += m0.y + m1.y;
        acc.z += m0.z + m1.z;
        acc.w += m0.w + m1.w;
    }
    if (p < p1) {
        float4 m0 = edge_msg(d_epack[p], d4, bond, useH, sc, sh);
        acc.x += m0.x; acc.y += m0.y; acc.z += m0.z; acc.w += m0.w;
    }

    // split to bf16 hi/lo (packed cvts)
    uint32_t hp0 = cvt_bf16x2(acc.y, acc.x);
    uint32_t hp1 = cvt_bf16x2(acc.w, acc.z);
    float hf0 = __uint_as_float(hp0 << 16);
    float hf1 = __uint_as_float(hp0 & 0xffff0000u);
    float hf2 = __uint_as_float(hp1 << 16);
    float hf3 = __uint_as_float(hp1 & 0xffff0000u);
    uint32_t lp0 = cvt_bf16x2(acc.y - hf1, acc.x - hf0);
    uint32_t lp1 = cvt_bf16x2(acc.w - hf3, acc.z - hf2);
    *reinterpret_cast<uint2*>(d_Ah + (size_t)warp * D_ + d4) = make_uint2(hp0, hp1);
    *reinterpret_cast<uint2*>(d_Al + (size_t)warp * D_ + d4) = make_uint2(lp0, lp1);
}

// final layer: y = hpre*sc2+sh2 (no relu); hsum += y; pool hsum.
__global__ void k_apply_final(const int* __restrict__ batch, int statOff,
                              const float* __restrict__ g, const float* __restrict__ b,
                              float invM) {
    __shared__ float s_sc[D_], s_sh[D_];
    int tid = threadIdx.x;
    if (tid < D_) {
        const float* st = d_stats + statOff;
        float mean = st[tid] * invM;
        float var  = st[D_ + tid] * invM - mean * mean;
        float is   = rsqrtf(var + 1e-5f);
        float sc   = g[tid] * is;
        s_sc[tid] = sc;
        s_sh[tid] = b[tid] - mean * sc;
    }
    __syncthreads();

    int i = blockIdx.x * blockDim.x + tid;
    float4 p  = reinterpret_cast<const float4*>(d_hpre)[i];
    int c4 = i & 31;
    float4 sc = reinterpret_cast<const float4*>(s_sc)[c4];
    float4 sh = reinterpret_cast<const float4*>(s_sh)[c4];
    float4 y;
    y.x = fmaf(p.x, sc.x, sh.x);
    y.y = fmaf(p.y, sc.y, sh.y);
    y.z = fmaf(p.z, sc.z, sh.z);
    y.w = fmaf(p.w, sc.w, sh.w);
    float4 hs = reinterpret_cast<const float4*>(d_hsum)[i];
    hs.x += y.x; hs.y += y.y; hs.z += y.z; hs.w += y.w;
    int node = i >> 5;
    int q = i & 31;
    int gr = batch[node];
    red4(d_pool + (size_t)gr * D_ + q * 4, hs);
    if (q == 0) atomicAdd(&d_cnt[gr], 1.f);
}

__global__ void k_initbias(int id, const float* __restrict__ bias, int C, int n) {
    int i = blockIdx.x * blockDim.x + threadIdx.x;
    if (i < n) buf(id)[i] = bias[i % C];
}

__global__ void k_fc4(const float* __restrict__ w4, const float* __restrict__ b4,
                      float* __restrict__ out) {
    int g = blockIdx.x;
    int t = threadIdx.x;
    float acc = 0.f;
#pragma unroll
    for (int k = t; k < 512; k += 128)
        acc += fmaxf(d_zf3[(size_t)g * 512 + k], 0.f) * w4[k];
#pragma unroll
    for (int o = 16; o > 0; o >>= 1)
        acc += __shfl_down_sync(0xffffffffu, acc, o);
    __shared__ float sred[4];
    if ((t & 31) == 0) sred[t >> 5] = acc;
    __syncthreads();
    if (t == 0) out[g] = sred[0] + sred[1] + sred[2] + sred[3] + b4[0];
}

__global__ void k_cvtW2(const float* __restrict__ W1, const float* __restrict__ W2) {
    int idx = blockIdx.x * blockDim.x + threadIdx.x;
    const float* W; int K, Nc, wBase;
    if (idx < 4096)      { W = W1; K = 128; Nc = 256; wBase = 0; }
    else if (idx < 8192) { W = W2; K = 256; Nc = 128; wBase = 32768; idx -= 4096; }
    else return;
    int n  = idx / (K >> 3);
    int k0 = (idx % (K >> 3)) << 3;
    float v[8];
#pragma unroll
    for (int j = 0; j < 8; j++) v[j] = W[(size_t)(k0 + j) * Nc + n];
    uint4 uh = cvt8(v);
    size_t o = ((size_t)wBase + (size_t)n * K + k0) >> 3;
    reinterpret_cast<uint4*>(d_Wh)[o] = uh;
}

// ---------------- GEMM1: pre-split A, cp.async double-buffered (BM=128) ----
static constexpr int SSTR = 40;
static constexpr int TILE_B = 128 * SSTR * 2;
static constexpr int BUF_B  = 3 * TILE_B;
static constexpr int SMEM_PS = 2 * BUF_B;

__global__ __launch_bounds__(256, 2)
void k_mma_ps(int wBase, const float* __restrict__ bias, int cId,
              int M, int Nc, int K, int statOffOut) {
    extern __shared__ char smem_ps[];
    __shared__ float s_st[256];

    const int tid = threadIdx.x, lane = tid & 31, wid = tid >> 5;
    const int wm = wid >> 2, wn = wid & 3;
    const int mblk = blockIdx.y, nblk = blockIdx.x;
    const uint32_t sbase = smem_u32(smem_ps);

    float acc[4][4][4];
#pragma unroll
    for (int a = 0; a < 4; a++)
#pragma unroll
        for (int bq = 0; bq < 4; bq++)
#pragma unroll
            for (int c = 0; c < 4; c++) acc[a][bq][c] = 0.f;

    const int aoffb = ((lane & 15) * SSTR + ((lane >> 4) << 3)) * 2;
    const int piece = lane >> 3;
    const int boffb = (((lane & 7) + ((piece >> 1) << 3)) * SSTR + ((piece & 1) << 3)) * 2;

    const int nChunks = K >> 5;

    auto issue = [&](int kc, int bsel) {
        uint32_t aH = sbase + bsel * BUF_B;
        uint32_t aL = aH + TILE_B;
        uint32_t bH = aL + TILE_B;
#pragma unroll
        for (int it = 0; it < 2; it++) {
            int idx = it * 256 + tid;
            int r = idx >> 2;
            int c8 = (idx & 3) << 3;
            int soff = (r * SSTR + c8) * 2;
            int gr = mblk * 128 + r;
            int ok = (gr < M) ? 16 : 0;
            int grc = (gr < M) ? gr : (M - 1);
            size_t aoff = (size_t)grc * K + kc * 32 + c8;
            cp16(aH + soff, d_Ah + aoff, ok);
            cp16(aL + soff, d_Al + aoff, ok);
            cp16(bH + soff, d_Wh + wBase + (size_t)(nblk * 128 + r) * K + kc * 32 + c8, 16);
        }
        CP_COMMIT();
    };

    issue(0, 0);
    for (int kc = 0; kc < nChunks; kc++) {
        int bsel = kc & 1;
        if (kc + 1 < nChunks) {
            issue(kc + 1, bsel ^ 1);
            CP_WAIT1();
        } else {
            CP_WAIT0();
        }
        __syncthreads();

        uint32_t aH = sbase + bsel * BUF_B;
        uint32_t aL = aH + TILE_B;
        uint32_t bH = aL + TILE_B;
#pragma unroll
        for (int ks = 0; ks < 2; ks++) {
            const int kb = ks * 32;
            uint32_t a_h[4][4], a_l[4][4], b_h[4][2];
#pragma unroll
            for (int mi = 0; mi < 4; mi++) {
                int off = aoffb + kb + (wm * 64 + mi * 16) * (SSTR * 2);
                ldmx4(a_h[mi], aH + off);
                ldmx4(a_l[mi], aL + off);
            }
#pragma unroll
            for (int nj = 0; nj < 2; nj++) {
                int off = boffb + kb + (wn * 32 + nj * 16) * (SSTR * 2);
                uint32_t r4[4];
                ldmx4(r4, bH + off);
                b_h[nj * 2][0] = r4[0]; b_h[nj * 2][1] = r4[1];
                b_h[nj * 2 + 1][0] = r4[2]; b_h[nj * 2 + 1][1] = r4[3];
            }
#pragma unroll
            for (int mi = 0; mi < 4; mi++)
#pragma unroll
                for (int ni = 0; ni < 4; ni++) {
                    mma_bf16(acc[mi][ni], a_h[mi], b_h[ni]);
                    mma_bf16(acc[mi][ni], a_l[mi], b_h[ni]);
                }
        }
        __syncthreads();
    }

    float* C = buf(cId);
    float st_s[8], st_q[8];
#pragma unroll
    for (int j = 0; j < 8; j++) { st_s[j] = 0.f; st_q[j] = 0.f; }

#pragma unroll
    for (int mi = 0; mi < 4; mi++) {
        int row0 = mblk * 128 + wm * 64 + mi * 16 + (lane >> 2);
#pragma unroll
        for (int ni = 0; ni < 4; ni++) {
            int col = nblk * 128 + wn * 32 + ni * 8 + ((lane & 3) << 1);
            float b0 = bias[col], b1 = bias[col + 1];
            float v0 = acc[mi][ni][0] + b0, v1 = acc[mi][ni][1] + b1;
            float v2 = acc[mi][ni][2] + b0, v3 = acc[mi][ni][3] + b1;
            if (row0 < M) {
                *reinterpret_cast<float2*>(&C[(size_t)row0 * Nc + col]) = make_float2(v0, v1);
                st_s[ni * 2]     += v0; st_q[ni * 2]     += v0 * v0;
                st_s[ni * 2 + 1] += v1; st_q[ni * 2 + 1] += v1 * v1;
            }
            if (row0 + 8 < M) {
                *reinterpret_cast<float2*>(&C[(size_t)(row0 + 8) * Nc + col]) = make_float2(v2, v3);
                st_s[ni * 2]     += v2; st_q[ni * 2]     += v2 * v2;
                st_s[ni * 2 + 1] += v3; st_q[ni * 2 + 1] += v3 * v3;
            }
        }
    }

    __syncthreads();
    s_st[tid] = 0.f;
    __syncthreads();
#pragma unroll
    for (int j = 0; j < 8; j++) {
        int colLocal = wn * 32 + (j >> 1) * 8 + ((lane & 3) << 1) + (j & 1);
        atomicAdd(&s_st[colLocal], st_s[j]);
        atomicAdd(&s_st[128 + colLocal], st_q[j]);
    }
    __syncthreads();
    if (tid < 128) {
        atomicAdd(&d_stats[statOffOut + nblk * 128 + tid], s_st[tid]);
        atomicAdd(&d_stats[statOffOut + Nc + nblk * 128 + tid], s_st[128 + tid]);
    }
}

// ---------------- GEMM2: BM=128, pipelined B (cp.async), hoisted A LDG -----
__global__ __launch_bounds__(256, 2)
void k_mma2(int aId, int wBase, const float* __restrict__ bias, int cId,
            int M, int Nc, int K, int statOffOut,
            int statOffIn, const float* __restrict__ g, const float* __restrict__ b,
            float invM) {
    __shared__ __nv_bfloat16 As_h[128 * SSTR];
    __shared__ __nv_bfloat16 As_l[128 * SSTR];
    __shared__ __nv_bfloat16 Bs_h[2][128 * SSTR];
    __shared__ float s_st[256];
    __shared__ float s_sc1[256], s_sh1[256];

    const float* A = buf(aId);
    const int tid = threadIdx.x, lane = tid & 31, wid = tid >> 5;
    const int wm = wid >> 2, wn = wid & 3;
    const int mblk = blockIdx.y, nblk = blockIdx.x;

    if (tid < K) {
        const float* st = d_stats + statOffIn;
        float mean = st[tid] * invM;
        float var  = st[K + tid] * invM - mean * mean;
        float is   = rsqrtf(var + 1e-5f);
        float sc   = g[tid] * is;
        s_sc1[tid] = sc;
        s_sh1[tid] = b[tid] - mean * sc;
    }

    float acc[4][4][4];
#pragma unroll
    for (int a = 0; a < 4; a++)
#pragma unroll
        for (int bq = 0; bq < 4; bq++)
#pragma unroll
            for (int c = 0; c < 4; c++) acc[a][bq][c] = 0.f;

    const uint32_t sAh = smem_u32(As_h), sAl = smem_u32(As_l);
    const uint32_t sB0 = smem_u32(Bs_h);

    const int aoffb = ((lane & 15) * SSTR + ((lane >> 4) << 3)) * 2;
    const int piece = lane >> 3;
    const int boffb = (((lane & 7) + ((piece >> 1) << 3)) * SSTR + ((piece & 1) << 3)) * 2;

    const int nChunks = K >> 5;

    auto issueB = [&](int kc, int bsel) {
        uint32_t bH = sB0 + bsel * (uint32_t)(128 * SSTR * 2);
#pragma unroll
        for (int it = 0; it < 2; it++) {
            int idx = it * 256 + tid;
            int r = idx >> 2;
            int c8 = (idx & 3) << 3;
            cp16(bH + (uint32_t)(r * SSTR + c8) * 2,
                 d_Wh + wBase + (size_t)(nblk * 128 + r) * K + kc * 32 + c8, 16);
        }
        CP_COMMIT();
    };

    issueB(0, 0);
    __syncthreads();

    for (int kc = 0; kc < nChunks; kc++) {
        int bsel = kc & 1;

        float v[2][8];
        int sof[2];
#pragma unroll
        for (int it = 0; it < 2; it++) {
            int idx = it * 256 + tid;
            int r = idx >> 2;
            int c8 = (idx & 3) << 3;
            int gr = mblk * 128 + r;
            int gc = kc * 32 + c8;
            sof[it] = r * SSTR + c8;
#pragma unroll
            for (int j = 0; j < 8; j++) v[it][j] = 0.f;
            if (gr < M) {
                const float4* s = reinterpret_cast<const float4*>(A + (size_t)gr * K + gc);
                *reinterpret_cast<float4*>(v[it])     = s[0];
                *reinterpret_cast<float4*>(v[it] + 4) = s[1];
            }
        }
        if (kc + 1 < nChunks) issueB(kc + 1, bsel ^ 1);

#pragma unroll
        for (int it = 0; it < 2; it++) {
            int idx = it * 256 + tid;
            int gc = kc * 32 + ((idx & 3) << 3);
#pragma unroll
            for (int j = 0; j < 8; j++)
                v[it][j] = fmaxf(fmaf(v[it][j], s_sc1[gc + j], s_sh1[gc + j]), 0.f);
            uint4 uh, ul;
            split8(v[it], uh, ul);
            *reinterpret_cast<uint4*>(&As_h[sof[it]]) = uh;
            *reinterpret_cast<uint4*>(&As_l[sof[it]]) = ul;
        }

        if (kc + 1 < nChunks) CP_WAIT1(); else CP_WAIT0();
        __syncthreads();

        uint32_t bH = sB0 + bsel * (uint32_t)(128 * SSTR * 2);
#pragma unroll
        for (int ks = 0; ks < 2; ks++) {
            const int kb = ks * 32;
            uint32_t a_h[4][4], a_l[4][4], b_h[4][2];
#pragma unroll
            for (int mi = 0; mi < 4; mi++) {
                int off = aoffb + kb + (wm * 64 + mi * 16) * (SSTR * 2);
                ldmx4(a_h[mi], sAh + off);
                ldmx4(a_l[mi], sAl + off);
            }
#pragma unroll
            for (int nj = 0; nj < 2; nj++) {
                int off = boffb + kb + (wn * 32 + nj * 16) * (SSTR * 2);
                uint32_t r4[4];
                ldmx4(r4, bH + off);
                b_h[nj * 2][0] = r4[0]; b_h[nj * 2][1] = r4[1];
                b_h[nj * 2 + 1][0] = r4[2]; b_h[nj * 2 + 1][1] = r4[3];
            }
#pragma unroll
            for (int mi = 0; mi < 4; mi++)
#pragma unroll
                for (int ni = 0; ni < 4; ni++) {
                    mma_bf16(acc[mi][ni], a_h[mi], b_h[ni]);
                    mma_bf16(acc[mi][ni], a_l[mi], b_h[ni]);
                }
        }
        __syncthreads();
    }

    float* C = buf(cId);
    float st_s[8], st_q[8];
#pragma unroll
    for (int j = 0; j < 8; j++) { st_s[j] = 0.f; st_q[j] = 0.f; }

#pragma unroll
    for (int mi = 0; mi < 4; mi++) {
        int row0 = mblk * 128 + wm * 64 + mi * 16 + (lane >> 2);
#pragma unroll
        for (int ni = 0; ni < 4; ni++) {
            int col = nblk * 128 + wn * 32 + ni * 8 + ((lane & 3) << 1);
            float b0 = bias[col], b1 = bias[col + 1];
            float v0 = acc[mi][ni][0] + b0, v1 = acc[mi][ni][1] + b1;
            float v2 = acc[mi][ni][2] + b0, v3 = acc[mi][ni][3] + b1;
            if (row0 < M) {
                *reinterpret_cast<float2*>(&C[(size_t)row0 * Nc + col]) = make_float2(v0, v1);
                st_s[ni * 2]     += v0; st_q[ni * 2]     += v0 * v0;
                st_s[ni * 2 + 1] += v1; st_q[ni * 2 + 1] += v1 * v1;
            }
            if (row0 + 8 < M) {
                *reinterpret_cast<float2*>(&C[(size_t)(row0 + 8) * Nc + col]) = make_float2(v2, v3);
                st_s[ni * 2]     += v2; st_q[ni * 2]     += v2 * v2;
                st_s[ni * 2 + 1] += v3; st_q[ni * 2 + 1] += v3 * v3;
            }
        }
    }

    __syncthreads();
    s_st[tid] = 0.f;
    __syncthreads();
#pragma unroll
    for (int j = 0; j < 8; j++) {
        int colLocal = wn * 32 + (j >> 1) * 8 + ((lane & 3) << 1) + (j & 1);
        atomicAdd(&s_st[colLocal], st_s[j]);
        atomicAdd(&s_st[128 + colLocal], st_q[j]);
    }
    __syncthreads();
    if (tid < 128) {
        atomicAdd(&d_stats[statOffOut + nblk * 128 + tid], s_st[tid]);
        atomicAdd(&d_stats[statOffOut + Nc + nblk * 128 + tid], s_st[128 + tid]);
    }
}

// ---------------- FFMA2 SGEMM (FC head only) ----------------
// XF: 0 none, 1 relu, 3 pool/max(cnt,1)
template <int BM, int BN, int BK, int TM, int TN, int XF, bool ATOMIC>
__launch_bounds__((BM / TM) * (BN / TN))
__global__ void k_sgemm(int aId, const float* __restrict__ W,
                        const float* __restrict__ bias, int cId,
                        int M, int K, int Nc, int kLen) {
    constexpr int THREADS = (BM / TM) * (BN / TN);
    constexpr int PAD = 4;
    __shared__ float As[BK][BM + PAD];
    __shared__ float Ws[BK][BN];

    const float* A = (XF == 3) ? d_pool : buf(aId);
    float* C = buf(cId);

    const int tid  = threadIdx.x;
    const int tcol = tid % (BN / TN);
    const int trow = tid / (BN / TN);
    const int rowBase = blockIdx.y * BM;
    const int colBase = blockIdx.x * BN;
    const int kStart  = blockIdx.z * kLen;

    u64 acc2[TM / 2][TN];
#pragma unroll
    for (int i = 0; i < TM / 2; i++)
#pragma unroll
        for (int j = 0; j < TN; j++) acc2[i][j] = 0ull;

    constexpr int AROWS_PER   = (BM * BK) / THREADS;
    constexpr int AROW_STRIDE = THREADS / BK;
    constexpr int WROWS_PER   = (BK * BN) / THREADS;
    constexpr int WROW_STRIDE = THREADS / BN;

    const int aCol = tid % BK;
    const int aRow = tid / BK;
    const int wCol = tid % BN;
    const int wRow = tid / BN;

    for (int k0 = kStart; k0 < kStart + kLen; k0 += BK) {
        const int kk = k0 + aCol;
#pragma unroll
        for (int r = 0; r < AROWS_PER; r++) {
            int row = rowBase + aRow + r * AROW_STRIDE;
            float v = (row < M) ? A[(size_t)row * K + kk] : 0.f;
            if (XF == 1) v = fmaxf(v, 0.f);
            if (XF == 3 && row < M) v = v / fmaxf(d_cnt[row], 1.f);
            As[aCol][aRow + r * AROW_STRIDE] = v;
        }
#pragma unroll
        for (int r = 0; r < WROWS_PER; r++) {
            Ws[wRow + r * WROW_STRIDE][wCol] =
                W[(size_t)(k0 + wRow + r * WROW_STRIDE) * Nc + colBase + wCol];
        }
        __syncthreads();
#pragma unroll
        for (int kq = 0; kq < BK; kq++) {
            u64 a2[TM / 2];
            const u64* ap = reinterpret_cast<const u64*>(&As[kq][trow * TM]);
#pragma unroll
            for (int i = 0; i < TM / 2; i++) a2[i] = ap[i];
            float4 wv = *reinterpret_cast<const float4*>(&Ws[kq][tcol * TN]);
            float wf[4] = {wv.x, wv.y, wv.z, wv.w};
#pragma unroll
            for (int j = 0; j < TN; j++) {
                u64 wp = splat2(wf[j]);
#pragma unroll
                for (int i = 0; i < TM / 2; i++) fma2(acc2[i][j], a2[i], wp);
            }
        }
        __syncthreads();
    }

#pragma unroll
    for (int i = 0; i < TM / 2; i++) {
        int row0 = rowBase + trow * TM + 2 * i;
        float lo[TN], hi[TN];
#pragma unroll
        for (int j = 0; j < TN; j++) unpack2(acc2[i][j], lo[j], hi[j]);
        int col0 = colBase + tcol * TN;
        if (ATOMIC) {
            if (row0 < M) {
#pragma unroll
                for (int j = 0; j < TN; j++) atomicAdd(&C[(size_t)row0 * Nc + col0 + j], lo[j]);
            }
            if (row0 + 1 < M) {
#pragma unroll
                for (int j = 0; j < TN; j++) atomicAdd(&C[(size_t)(row0 + 1) * Nc + col0 + j], hi[j]);
            }
        } else {
            float bc[TN];
#pragma unroll
            for (int j = 0; j < TN; j++) bc[j] = bias[col0 + j];
            if (row0 < M) {
#pragma unroll
                for (int j = 0; j < TN; j++) C[(size_t)row0 * Nc + col0 + j] = lo[j] + bc[j];
            }
            if (row0 + 1 < M) {
#pragma unroll
                for (int j = 0; j < TN; j++) C[(size_t)(row0 + 1) * Nc + col0 + j] = hi[j] + bc[j];
            }
        }
    }
}

// ---------------- launch ----------------
extern "C" void kernel_launch(void* const* d_in, const int* in_sizes, int n_in,
                              void* d_out, int out_size) {
    const int*   x        = (const int*)  d_in[0];
    const int*   ei       = (const int*)  d_in[1];
    const int*   ea       = (const int*)  d_in[2];
    const int*   batch    = (const int*)  d_in[3];
    const float* atom_emb = (const float*)d_in[4];
    const float* bond_emb = (const float*)d_in[5];
    const float* eps      = (const float*)d_in[6];
    const float* W1       = (const float*)d_in[7];
    const float* b1       = (const float*)d_in[8];
    const float* g1       = (const float*)d_in[9];
    const float* be1      = (const float*)d_in[10];
    const float* W2       = (const float*)d_in[11];
    const float* b2       = (const float*)d_in[12];
    const float* bn_g     = (const float*)d_in[13];
    const float* bn_b     = (const float*)d_in[14];
    const float* fcW1     = (const float*)d_in[15];
    const float* fcb1     = (const float*)d_in[16];
    const float* fcW2     = (const float*)d_in[17];
    const float* fcb2     = (const float*)d_in[18];
    const float* fcW3     = (const float*)d_in[19];
    const float* fcb3     = (const float*)d_in[20];
    const float* fcW4     = (const float*)d_in[21];
    const float* fcb4     = (const float*)d_in[22];
    float* out = (float*)d_out;

    const float invN = 1.f / (float)N_;

    static bool attrSet = false;
    if (!attrSet) {
        cudaFuncSetAttribute(k_mma_ps, cudaFuncAttributeMaxDynamicSharedMemorySize, SMEM_PS);
        attrSet = true;
    }

    // setup + CSR build
    k_zero_all<<<(L_ * 1024 + G_ * D_ + G_ + N_ + 255) / 256, 256>>>();
    k_cvtW2<<<(8192 + 255) / 256, 256>>>(W1, W2);
    k_cvtBond<<<(BONDE / 8 + 255) / 256, 256>>>(bond_emb);
    k_atom<<<(N_ * 32 + 255) / 256, 256>>>(x, atom_emb);
    k_hist<<<(E_ + 255) / 256, 256>>>(ei);
    k_scan<<<1, 1024>>>();
    k_scatter<<<(E_ + 255) / 256, 256>>>(ei, ea);

    for (int l = 0; l < L_; l++) {
        // gather: fused prev-BN finalize + hsum + pull aggregation (bf16 bond)
        k_gather<<<(N_ * 32 + 255) / 256, 256>>>(l * 3 * V_ * D_, eps, l,
                                                 l == 0 ? 1 : 0,
                                                 (l - 1) * 1024 + 512,
                                                 bn_g + (l - 1) * D_, bn_b + (l - 1) * D_,
                                                 invN);

        // GEMM1: z1 = (Ah+Al) @ W1 + b1, cp.async double-buffered, fused stats
        k_mma_ps<<<dim3(2, MBLKS), 256, SMEM_PS>>>(0, b1, 3, N_, 256, 128, l * 1024);

        // GEMM2 (pipelined): hpre = relu(bn1(z1)) @ W2 + b2, bn1 finalize fused
        k_mma2<<<dim3(1, MBLKS), 256>>>(3, 32768, b2, 4, N_, 128, 256,
                                        l * 1024 + 512, l * 1024, g1, be1, invN);
    }

    // final layer: y (no relu) + hsum + pool
    k_apply_final<<<(N_ * 32) / 256, 256>>>(batch, (L_ - 1) * 1024 + 512,
                                            bn_g + (L_ - 1) * D_, bn_b + (L_ - 1) * D_, invN);

    // FC head (fc1 reads pool/cnt directly)
    k_sgemm<64, 64, 16, 4, 4, 3, false>
        <<<dim3(1024 / 64, G_ / 64, 1), 256>>>(10, fcW1, fcb1, 13, G_, 128, 1024, 128);

    k_initbias<<<(G_ * 1024) / 256, 256>>>(14, fcb2, 1024, G_ * 1024);
    k_sgemm<64, 64, 16, 4, 4, 1, true>
        <<<dim3(1024 / 64, G_ / 64, 8), 256>>>(13, fcW2, nullptr, 14, G_, 1024, 1024, 128);

    k_initbias<<<(G_ * 512) / 256, 256>>>(15, fcb3, 512, G_ * 512);
    k_sgemm<64, 64, 16, 4, 4, 1, true>
        <<<dim3(512 / 64, G_ / 64, 8), 256>>>(14, fcW3, nullptr, 15, G_, 1024, 512, 128);

    k_fc4<<<G_, 128>>>(fcW4, fcb4, out);
}